// round 6
// baseline (speedup 1.0000x reference)
#include <cuda_runtime.h>
#include <cuda_fp16.h>
#include <cstdint>

#define DINL __device__ __forceinline__

namespace {
constexpr int Tn = 187;
constexpr int Hn = 256;
constexpr int BM = 128;          // batch rows per CTA
constexpr int NT = 128;          // 4 warps x 32 rows each

constexpr int WH_STRIDE = 528;   // bytes per Wh row (264 f16) -> conflict-free ldsm.trans
constexpr int W1_STRIDE = 144;   // bytes per W1 row (72 f16)

constexpr int OFF_WH   = 0;
constexpr int OFF_HBUF = OFF_WH + Hn * WH_STRIDE;   // 135168, 64KB h round-trip buffer
constexpr int OFF_WXB  = OFF_HBUF + 65536;          // 200704, float2{Wx,b} x256
constexpr int OFF_B1   = OFF_WXB + Hn * 8;          // 202752
constexpr int OFF_W2   = OFF_B1 + 64 * 4;           // 203008
constexpr int OFF_B2   = OFF_W2 + 320 * 4;          // 204288
constexpr int SMEM_TOTAL = OFF_B2 + 32;             // 204320
static_assert(SMEM_TOTAL <= 232448, "smem overflow");
static_assert(Hn * 64 * 2 <= 65536, "W1 must fit in h buffer");
}

// ---------------- helpers ----------------
DINL uint32_t smem_u32(const void* p) {
    uint32_t a;
    asm("{ .reg .u64 t; cvta.to.shared.u64 t, %1; cvt.u32.u64 %0, t; }" : "=r"(a) : "l"(p));
    return a;
}
DINL void ldsm4t(uint32_t& r0, uint32_t& r1, uint32_t& r2, uint32_t& r3, uint32_t addr) {
    asm volatile("ldmatrix.sync.aligned.m8n8.x4.trans.shared.b16 {%0,%1,%2,%3}, [%4];"
                 : "=r"(r0), "=r"(r1), "=r"(r2), "=r"(r3) : "r"(addr));
}
DINL void mma16816(float* d, uint32_t a0, uint32_t a1, uint32_t a2, uint32_t a3,
                   uint32_t b0, uint32_t b1) {
    asm volatile("mma.sync.aligned.m16n8k16.row.col.f32.f16.f16.f32 "
                 "{%0,%1,%2,%3}, {%4,%5,%6,%7}, {%8,%9}, {%0,%1,%2,%3};"
                 : "+f"(d[0]), "+f"(d[1]), "+f"(d[2]), "+f"(d[3])
                 : "r"(a0), "r"(a1), "r"(a2), "r"(a3), "r"(b0), "r"(b1));
}
DINL uint32_t pack_f16x2(float lo, float hi) {
    uint32_t r;
    asm("cvt.rn.f16x2.f32 %0, %1, %2;" : "=r"(r) : "f"(hi), "f"(lo));
    return r;
}
DINL uint32_t tanh2(uint32_t v) {
    uint32_t r;
    asm("tanh.approx.f16x2 %0, %1;" : "=r"(r) : "r"(v));
    return r;
}

// ---------------- kernel ----------------
__global__ void __launch_bounds__(NT, 1)
rnn_kernel(const float* __restrict__ gx,  const float* __restrict__ gWx,
           const float* __restrict__ gWh, const float* __restrict__ gbr,
           const float* __restrict__ gW1, const float* __restrict__ gb1,
           const float* __restrict__ gW2, const float* __restrict__ gb2,
           float* __restrict__ gout) {
    extern __shared__ char smem[];
    const int tid  = threadIdx.x;
    const int lane = tid & 31;
    const int wid  = tid >> 5;
    const int m0   = blockIdx.x * BM;
    const int gid  = lane >> 2;      // row group 0..7
    const int tig  = lane & 3;       // thread-in-group

    // ---- cooperative staging ----
    for (int i = tid; i < Hn * Hn; i += NT) {            // Wh[k][n] -> k-major padded f16
        int k = i >> 8, n = i & 255;
        *(__half*)(smem + OFF_WH + k * WH_STRIDE + n * 2) = __float2half(gWh[i]);
    }
    for (int i = tid; i < Hn; i += NT)
        ((float2*)(smem + OFF_WXB))[i] = make_float2(gWx[i], gbr[i]);
    for (int i = tid; i < 64; i += NT)  ((float*)(smem + OFF_B1))[i] = gb1[i];
    for (int i = tid; i < 320; i += NT) ((float*)(smem + OFF_W2))[i] = gW2[i];
    if (tid < 5) ((float*)(smem + OFF_B2))[tid] = gb2[tid];
    __syncthreads();

    // ---- per-warp setup ----
    const uint32_t sb = smem_u32(smem);
    const int tq = lane >> 3;
    const uint32_t lds_wh = sb + OFF_WH + ((tq & 1) * 8 + (lane & 7)) * WH_STRIDE + (tq >> 1) * 16;
    const float4* wxb4 = (const float4*)(smem + OFF_WXB);   // {w0,b0,w1,b1} per even col pair
    const size_t rbase = (size_t)(m0 + wid * 32 + gid) * Tn; // rows: +0,+8,+16,+24 (x8*Tn)

    // hA: A fragments for M=32 (two m16 tiles). hA[kc*8 + j], j=0..3 tile0 (rows gid,gid+8),
    // j=4..7 tile1 (rows gid+16, gid+24). Pairs of f16 cols (2tig, 2tig+1) per k8 block.
    uint32_t hA[128];

    // ---- t = 0: h0 = tanh(x0*Wx + b) ----
    float xn[4];
    #pragma unroll
    for (int j = 0; j < 4; ++j) xn[j] = gx[rbase + (size_t)(8 * j) * Tn];
    #pragma unroll
    for (int g = 0; g < 8; ++g) {
        #pragma unroll
        for (int u = 0; u < 4; ++u) {
            int t2 = 4 * g + u;
            float4 wb = wxb4[(8 * t2 + 2 * tig) >> 1];
            int base = 16 * g + (u >> 1) * 8 + (u & 1) * 2;
            hA[base + 0] = tanh2(pack_f16x2(fmaf(xn[0], wb.x, wb.y), fmaf(xn[0], wb.z, wb.w)));
            hA[base + 1] = tanh2(pack_f16x2(fmaf(xn[1], wb.x, wb.y), fmaf(xn[1], wb.z, wb.w)));
            hA[base + 4] = tanh2(pack_f16x2(fmaf(xn[2], wb.x, wb.y), fmaf(xn[2], wb.z, wb.w)));
            hA[base + 5] = tanh2(pack_f16x2(fmaf(xn[3], wb.x, wb.y), fmaf(xn[3], wb.z, wb.w)));
        }
    }
    #pragma unroll
    for (int j = 0; j < 4; ++j) xn[j] = gx[rbase + (size_t)(8 * j) * Tn + 1];

    // ---- recurrence: t = 1..186 (warp-private, no sync) ----
    #pragma unroll 1
    for (int t = 1; t < Tn; ++t) {
        float xv[4];
        #pragma unroll
        for (int j = 0; j < 4; ++j) xv[j] = xn[j];
        const int tnext = (t + 1 < Tn) ? t + 1 : t;       // prefetch next step's x
        #pragma unroll
        for (int j = 0; j < 4; ++j) xn[j] = gx[rbase + (size_t)(8 * j) * Tn + tnext];

        #pragma unroll
        for (int g = 0; g < 8; ++g) {                     // 32-col n-group: n8-tiles 4g..4g+3
            float dA[4][4], dB[4][4];
            #pragma unroll
            for (int q = 0; q < 4; ++q) {                 // D init = x_t*Wx + b
                float4 wb = wxb4[(8 * (4 * g + q) + 2 * tig) >> 1];
                dA[q][0] = fmaf(xv[0], wb.x, wb.y); dA[q][1] = fmaf(xv[0], wb.z, wb.w);
                dA[q][2] = fmaf(xv[1], wb.x, wb.y); dA[q][3] = fmaf(xv[1], wb.z, wb.w);
                dB[q][0] = fmaf(xv[2], wb.x, wb.y); dB[q][1] = fmaf(xv[2], wb.z, wb.w);
                dB[q][2] = fmaf(xv[3], wb.x, wb.y); dB[q][3] = fmaf(xv[3], wb.z, wb.w);
            }
            #pragma unroll
            for (int kc = 0; kc < 16; ++kc) {
                const uint32_t a0 = hA[8 * kc],     a1 = hA[8 * kc + 1];
                const uint32_t a2 = hA[8 * kc + 2], a3 = hA[8 * kc + 3];
                const uint32_t a4 = hA[8 * kc + 4], a5 = hA[8 * kc + 5];
                const uint32_t a6 = hA[8 * kc + 6], a7 = hA[8 * kc + 7];
                const uint32_t base = lds_wh + kc * 16 * WH_STRIDE + g * 64;
                #pragma unroll
                for (int qq = 0; qq < 2; ++qq) {          // n16 tile = n8 tiles 2qq, 2qq+1
                    uint32_t b0, b1, b2, b3;
                    ldsm4t(b0, b1, b2, b3, base + qq * 32);
                    mma16816(dA[2 * qq],     a0, a1, a2, a3, b0, b1);
                    mma16816(dA[2 * qq + 1], a0, a1, a2, a3, b2, b3);
                    mma16816(dB[2 * qq],     a4, a5, a6, a7, b0, b1);
                    mma16816(dB[2 * qq + 1], a4, a5, a6, a7, b2, b3);
                }
            }
            // pack -> tanh -> SMEM (A-frag flat order for this group's 2 kc blocks)
            uint32_t L[16];
            #pragma unroll
            for (int q = 0; q < 4; ++q) {
                int base = (q >> 1) * 8 + (q & 1) * 2;
                L[base + 0] = tanh2(pack_f16x2(dA[q][0], dA[q][1]));
                L[base + 1] = tanh2(pack_f16x2(dA[q][2], dA[q][3]));
                L[base + 4] = tanh2(pack_f16x2(dB[q][0], dB[q][1]));
                L[base + 5] = tanh2(pack_f16x2(dB[q][2], dB[q][3]));
            }
            #pragma unroll
            for (int c = 0; c < 4; ++c)
                *(uint4*)(smem + OFF_HBUF + (((4 * g + c) * NT + tid) << 4)) =
                    make_uint4(L[4 * c], L[4 * c + 1], L[4 * c + 2], L[4 * c + 3]);
        }
        // reload next-step A fragments (thread-private, ordered vs own STS)
        #pragma unroll
        for (int c = 0; c < 32; ++c) {
            uint4 v = *(const uint4*)(smem + OFF_HBUF + ((c * NT + tid) << 4));
            hA[4 * c] = v.x; hA[4 * c + 1] = v.y; hA[4 * c + 2] = v.z; hA[4 * c + 3] = v.w;
        }
    }

    // ---- head: stage W1 into dead h-buffer, hidden = relu(h@W1+b1), W2 + softmax ----
    __syncthreads();
    for (int i = tid; i < Hn * 64; i += NT) {             // W1[k][n]
        int k = i >> 6, n = i & 63;
        *(__half*)(smem + OFF_HBUF + k * W1_STRIDE + n * 2) = __float2half(gW1[i]);
    }
    __syncthreads();
    const uint32_t lds_w1 = sb + OFF_HBUF + ((tq & 1) * 8 + (lane & 7)) * W1_STRIDE + (tq >> 1) * 16;

    float hdA[8][4], hdB[8][4];
    #pragma unroll
    for (int t2 = 0; t2 < 8; ++t2)
        #pragma unroll
        for (int c = 0; c < 4; ++c) { hdA[t2][c] = 0.f; hdB[t2][c] = 0.f; }
    #pragma unroll
    for (int kc = 0; kc < 16; ++kc) {
        const uint32_t a0 = hA[8 * kc],     a1 = hA[8 * kc + 1];
        const uint32_t a2 = hA[8 * kc + 2], a3 = hA[8 * kc + 3];
        const uint32_t a4 = hA[8 * kc + 4], a5 = hA[8 * kc + 5];
        const uint32_t a6 = hA[8 * kc + 6], a7 = hA[8 * kc + 7];
        const uint32_t base = lds_w1 + kc * 16 * W1_STRIDE;
        #pragma unroll
        for (int nt2 = 0; nt2 < 4; ++nt2) {
            uint32_t b0, b1, b2, b3;
            ldsm4t(b0, b1, b2, b3, base + nt2 * 32);
            mma16816(hdA[2 * nt2],     a0, a1, a2, a3, b0, b1);
            mma16816(hdA[2 * nt2 + 1], a0, a1, a2, a3, b2, b3);
            mma16816(hdB[2 * nt2],     a4, a5, a6, a7, b0, b1);
            mma16816(hdB[2 * nt2 + 1], a4, a5, a6, a7, b2, b3);
        }
    }
    {
        const float* sb1 = (const float*)(smem + OFF_B1);
        const float* sw2 = (const float*)(smem + OFF_W2);
        const float* sb2 = (const float*)(smem + OFF_B2);
        float acc[4][5];
        #pragma unroll
        for (int j = 0; j < 4; ++j)
            #pragma unroll
            for (int c = 0; c < 5; ++c) acc[j][c] = 0.f;
        #pragma unroll
        for (int t2 = 0; t2 < 8; ++t2) {
            int c0 = 8 * t2 + 2 * tig;
            float b1a = sb1[c0], b1b = sb1[c0 + 1];
            float hv[4][2] = {
                { fmaxf(hdA[t2][0] + b1a, 0.f), fmaxf(hdA[t2][1] + b1b, 0.f) },
                { fmaxf(hdA[t2][2] + b1a, 0.f), fmaxf(hdA[t2][3] + b1b, 0.f) },
                { fmaxf(hdB[t2][0] + b1a, 0.f), fmaxf(hdB[t2][1] + b1b, 0.f) },
                { fmaxf(hdB[t2][2] + b1a, 0.f), fmaxf(hdB[t2][3] + b1b, 0.f) } };
            #pragma unroll
            for (int j = 0; j < 4; ++j)
                #pragma unroll
                for (int c = 0; c < 5; ++c)
                    acc[j][c] = fmaf(hv[j][0], sw2[c0 * 5 + c],
                               fmaf(hv[j][1], sw2[(c0 + 1) * 5 + c], acc[j][c]));
        }
        #pragma unroll
        for (int j = 0; j < 4; ++j)
            #pragma unroll
            for (int c = 0; c < 5; ++c) {
                acc[j][c] += __shfl_xor_sync(0xFFFFFFFFu, acc[j][c], 1);
                acc[j][c] += __shfl_xor_sync(0xFFFFFFFFu, acc[j][c], 2);
            }
        if (tig == 0) {
            #pragma unroll
            for (int j = 0; j < 4; ++j) {
                size_t row = (size_t)(m0 + wid * 32 + gid + 8 * j);
                float o[5];
                #pragma unroll
                for (int c = 0; c < 5; ++c) o[c] = acc[j][c] + sb2[c];
                float mx = fmaxf(fmaxf(fmaxf(o[0], o[1]), fmaxf(o[2], o[3])), o[4]);
                float s = 0.f;
                #pragma unroll
                for (int c = 0; c < 5; ++c) { o[c] = __expf(o[c] - mx); s += o[c]; }
                float inv = 1.f / s;
                #pragma unroll
                for (int c = 0; c < 5; ++c) gout[row * 5 + c] = o[c] * inv;
            }
        }
    }
}

// ---------------- launch ----------------
extern "C" void kernel_launch(void* const* d_in, const int* in_sizes, int n_in,
                              void* d_out, int out_size) {
    const float* x  = (const float*)d_in[0];
    const float* Wx = (const float*)d_in[1];
    const float* Wh = (const float*)d_in[2];
    const float* br = (const float*)d_in[3];
    const float* W1 = (const float*)d_in[4];
    const float* b1 = (const float*)d_in[5];
    const float* W2 = (const float*)d_in[6];
    const float* b2 = (const float*)d_in[7];

    cudaFuncSetAttribute(rnn_kernel, cudaFuncAttributeMaxDynamicSharedMemorySize, SMEM_TOTAL);
    rnn_kernel<<<256, NT, SMEM_TOTAL>>>(x, Wx, Wh, br, W1, b1, W2, b2, (float*)d_out);
}